// round 15
// baseline (speedup 1.0000x reference)
#include <cuda_runtime.h>
#include <cuda_fp16.h>
#include <math.h>

#define NSTEP 256
#define G 4
#define NCTA 128
#define NTHREADS 512

#define W1F_JOBS 186
#define W1F_U4   (W1F_JOBS * 4 * 32)
__device__ uint4 g_W1f[W1F_U4];

// ---- shared memory layout (float offsets) ----
#define RING_OFF   0
#define RH_OFF     512
#define WHH_OFF    12032
#define WAIH_OFF   20224
#define WAHH_OFF   22272
#define W2S_OFF    24320
#define WIH_OFF    25408
#define BE_OFF     25920
#define PSB_OFF    26432
#define PSA_OFF    29504
#define PSA2_OFF   31808
#define E1S_OFF    34112
#define NC_OFF     34368
#define B1S_OFF    34880
#define BAC_OFF    34944
#define WGS_OFF    35072
#define WOS_OFF    35200
#define EHS_OFF    35328
#define ECS_OFF    35392
#define AHS_OFF    35456
#define ACS_OFF    35584
#define AIS_OFF    35712
#define GSM_OFF    35776
#define OSM_OFF    35808
#define ERRH_OFF   35840
#define B2S_OFF    35880
#define BGS_OFF    35896
#define BOS_OFF    35904
#define PRED_OFF   35912
#define THETA_OFF  35916
#define W01_OFF    35920
#define WSTG_OFF   45136
#define SMEM_FLOATS 57424
#define SMEM_BYTES  (SMEM_FLOATS * 4)

__device__ __forceinline__ float tanhfast(float v) {
    float r;
    asm("tanh.approx.f32 %0, %1;" : "=f"(r) : "f"(v));
    return r;
}
__device__ __forceinline__ float sigf(float v) {
    return fmaf(tanhfast(0.5f * v), 0.5f, 0.5f);
}

__global__ void build_w1f(const float* __restrict__ W1) {
    int idx = blockIdx.x * 256 + threadIdx.x;
    if (idx >= W1F_U4) return;
    int lane = idx & 31;
    int jt   = (idx >> 5) & 3;
    int job  = idx >> 7;
    int r  = lane >> 2;
    int tg = lane & 3;
    float f[8];
    #pragma unroll
    for (int i = 0; i < 8; ++i) f[i] = 0.0f;
    if (job < 180) {
        int m  = job / 9;
        int kb = job - m * 9;
        int j0 = jt * 16;
        int kbase = kb * 16;
        const int dj[8] = {r, r, r + 8, r + 8, r, r, r + 8, r + 8};
        const int dc[8] = {2*tg, 2*tg+1, 2*tg, 2*tg+1, 2*tg+8, 2*tg+9, 2*tg+8, 2*tg+9};
        #pragma unroll
        for (int i = 0; i < 8; ++i) {
            int kc = kbase + dc[i];
            if (kc < 129) f[i] = W1[(j0 + dj[i]) * 2580 + m * 129 + kc];
        }
    }
    __half h[8];
    #pragma unroll
    for (int i = 0; i < 8; ++i) h[i] = __float2half(f[i]);
    uint4 u;
    u.x = *reinterpret_cast<unsigned int*>(&h[0]);
    u.y = *reinterpret_cast<unsigned int*>(&h[2]);
    u.z = *reinterpret_cast<unsigned int*>(&h[4]);
    u.w = *reinterpret_cast<unsigned int*>(&h[6]);
    g_W1f[idx] = u;
}

#define MMA16816(d, a, bx, by) \
    asm volatile("mma.sync.aligned.m16n8k16.row.col.f32.f16.f16.f32 " \
        "{%0,%1,%2,%3}, {%4,%5,%6,%7}, {%8,%9}, {%0,%1,%2,%3};" \
        : "+f"(d[0]), "+f"(d[1]), "+f"(d[2]), "+f"(d[3]) \
        : "r"(a.x), "r"(a.y), "r"(a.z), "r"(a.w), "r"(bx), "r"(by))

// NOTE "memory" clobber: without it the compiler may sink staged-buffer reads
// past the next cp.async into the same slot (the R11-R14 corruption).
#define CP_ASYNC16(saddr, gptr) \
    asm volatile("cp.async.cg.shared.global [%0], [%1], 16;" \
        :: "r"(saddr), "l"((const void*)(gptr)) : "memory")
#define CP_COMMIT() asm volatile("cp.async.commit_group;" ::: "memory")
#define CP_WAIT1()  asm volatile("cp.async.wait_group 1;" ::: "memory")
#define CP_WAIT0()  asm volatile("cp.async.wait_group 0;" ::: "memory")

#define LDSU4(v, a) \
    asm volatile("ld.shared.v4.u32 {%0,%1,%2,%3}, [%4];" \
        : "=r"(v.x), "=r"(v.y), "=r"(v.z), "=r"(v.w) : "r"(a))

#define ISSUE_JOB(GW, STG, JOBIDX, BUF) do { \
    const uint4* _gp = (GW) + (JOBIDX) * 128; \
    CP_ASYNC16((STG) + (BUF) * 2048 +    0, _gp); \
    CP_ASYNC16((STG) + (BUF) * 2048 +  512, _gp + 32); \
    CP_ASYNC16((STG) + (BUF) * 2048 + 1024, _gp + 64); \
    CP_ASYNC16((STG) + (BUF) * 2048 + 1536, _gp + 96); \
    CP_COMMIT(); \
} while (0)

// 14 pre-barrier jobs (m>=2) for step t+1, launched at end of step t with
// sP = s(t): row m reads slot sP+m-1 = s(t+1)+m  (correct phase).
__device__ __forceinline__ void prejobs_ca(int sP, int w, int lane,
    unsigned int stg, const unsigned int* __restrict__ rhU,
    float (&d0)[4], float (&d1)[4], float (&d2)[4], float (&d3)[4])
{
    const int J0 = 18 + w * 14;
    int m  = J0 / 9;
    int kb = J0 - m * 9;
    int slot = sP + m - 1;
    if (slot >= 20) slot -= 20;
    const uint4* gw = g_W1f + J0 * 128 + lane;

    ISSUE_JOB(gw, stg, 0, 0);
    ISSUE_JOB(gw, stg, 1, 1);
    #pragma unroll
    for (int it = 0; it < 14; ++it) {
        if (it < 13) { CP_WAIT1(); } else { CP_WAIT0(); }
        unsigned int rd = stg + (unsigned int)((it & 1) * 2048);
        uint4 a0, a1, a2, a3;
        LDSU4(a0, rd);
        LDSU4(a1, rd + 512);
        LDSU4(a2, rd + 1024);
        LDSU4(a3, rd + 1536);
        int bofs = ((slot * 9 + kb) * 32 + lane) * 2;
        unsigned int bx = rhU[bofs], by = rhU[bofs + 1];
        MMA16816(d0, a0, bx, by);
        MMA16816(d1, a1, bx, by);
        MMA16816(d2, a2, bx, by);
        MMA16816(d3, a3, bx, by);
        if (it < 12) ISSUE_JOB(gw, stg, it + 2, (it & 1));
        ++kb; if (kb == 9) { kb = 0; ++slot; if (slot == 20) slot = 0; }
    }
}

__device__ __forceinline__ void store_partials(float* __restrict__ base, int lane,
    const float (&d0)[4], const float (&d1)[4],
    const float (&d2)[4], const float (&d3)[4])
{
    int tg = lane & 3, gr = lane >> 2;
    if (tg < 2) {
        float* pb = base + 2 * tg;
        pb[(gr     ) * 4] = d0[0]; pb[(gr     ) * 4 + 1] = d0[1];
        pb[(gr +  8) * 4] = d0[2]; pb[(gr +  8) * 4 + 1] = d0[3];
        pb[(gr + 16) * 4] = d1[0]; pb[(gr + 16) * 4 + 1] = d1[1];
        pb[(gr + 24) * 4] = d1[2]; pb[(gr + 24) * 4 + 1] = d1[3];
        pb[(gr + 32) * 4] = d2[0]; pb[(gr + 32) * 4 + 1] = d2[1];
        pb[(gr + 40) * 4] = d2[2]; pb[(gr + 40) * 4 + 1] = d2[3];
        pb[(gr + 48) * 4] = d3[0]; pb[(gr + 48) * 4 + 1] = d3[1];
        pb[(gr + 56) * 4] = d3[2]; pb[(gr + 56) * 4 + 1] = d3[3];
    }
}

__global__ __launch_bounds__(NTHREADS, 1)
void mmoe_main(
    const float* __restrict__ x,      const float* __restrict__ pred0,
    const float* __restrict__ gate0,
    const float* __restrict__ W_ih,   const float* __restrict__ W_hh,
    const float* __restrict__ b_ih,   const float* __restrict__ b_hh,
    const float* __restrict__ W_o,    const float* __restrict__ b_o,
    const float* __restrict__ W1,     const float* __restrict__ b1,
    const float* __restrict__ W2,     const float* __restrict__ b2,
    const float* __restrict__ Wg,     const float* __restrict__ bg,
    const float* __restrict__ Wa_ih,  const float* __restrict__ Wa_hh,
    const float* __restrict__ ba_ih,  const float* __restrict__ ba_hh,
    float* __restrict__ out)
{
    extern __shared__ float sm[];
    __half* rh = reinterpret_cast<__half*>(&sm[RH_OFF]);
    const int tid = threadIdx.x;
    const int b0  = blockIdx.x * G;

    // ---------- init shared ----------
    if (tid < 512) sm[RING_OFF + tid] = 0.0f;
    for (int i = tid; i < 23040; i += NTHREADS) {
        int q = i & 3, ln = (i >> 2) & 31, kb = (i >> 7) % 9;
        bool is05 = (q == 0) && ((ln & 3) == 0) && (ln < 16) && (kb == 8);
        rh[i] = __float2half(is05 ? 0.5f : 0.0f);
    }
    for (int i = tid; i < 8192; i += NTHREADS) {
        int q = i & 3, h = (i >> 2) & 15, c = (i >> 6) & 7, k = i >> 9;
        sm[WHH_OFF + i] = W_hh[(c * 64 + q * 16 + h) * 16 + k];
    }
    {
        uint4* w01 = reinterpret_cast<uint4*>(&sm[W01_OFF]);
        for (int i = tid; i < 18 * 128; i += NTHREADS) w01[i] = g_W1f[i];
    }
    for (int i = tid; i < 2048; i += NTHREADS) {
        sm[WAIH_OFF + i] = Wa_ih[i];
        sm[WAHH_OFF + i] = Wa_hh[i];
    }
    for (int i = tid; i < 1088; i += NTHREADS) {
        int j2 = i / 68, k = i - j2 * 68;
        sm[W2S_OFF + i] = (k < 64) ? W2[j2 * 64 + k] : 0.0f;
    }
    if (tid < 512) {
        int q = tid & 3, h = (tid >> 2) & 15, c = tid >> 6;
        int gidx = c * 64 + q * 16 + h;
        sm[WIH_OFF + tid] = W_ih[gidx];
        sm[BE_OFF + tid]  = b_ih[gidx] + b_hh[gidx];
    }
    if (tid < 256) {
        int jj = tid >> 2;
        sm[PSA2_OFF + tid] = 0.5f * W1[jj * 2580 + 129 + 128];
        #pragma unroll
        for (int c = 1; c < 9; ++c) sm[PSA2_OFF + c * 256 + tid] = 0.0f;
    }
    if (tid < 128) {
        sm[BAC_OFF + tid] = ba_ih[tid] + ba_hh[tid];
        sm[WGS_OFF + tid] = Wg[tid];
        sm[WOS_OFF + tid] = W_o[tid];
        sm[AHS_OFF + tid] = 0.0f;
        sm[ACS_OFF + tid] = 0.0f;
    }
    if (tid < 64) { sm[B1S_OFF + tid] = b1[tid]; sm[EHS_OFF + tid] = 0.0f; sm[ECS_OFF + tid] = 0.0f; }
    if (tid < 40) sm[ERRH_OFF + tid] = 0.5f;
    if (tid < 32) sm[GSM_OFF + tid] = gate0[b0 * 8 + tid];
    if (tid < 16) sm[B2S_OFF + tid] = b2[tid];
    if (tid < 8)  { sm[BGS_OFF + tid] = bg[tid]; sm[BOS_OFF + tid] = b_o[tid]; }
    if (tid < 4)  sm[PRED_OFF + tid] = pred0[b0 + tid];
    __syncthreads();

    if (tid < 128) {
        // ====================== SMALL GROUP: warps 0-3 ======================
        int head = 0;
        for (int t = 0; t < NSTEP; ++t) {
            int s = head - 1; if (s < 0) s = 19;

            // ---- phase 2: experts ----
            {
                int c = tid >> 4, h = tid & 15;
                int ch4 = (c * 16 + h) * 4;
                float be[4], wi[4];
                *reinterpret_cast<float4*>(be) = *(const float4*)&sm[BE_OFF + ch4];
                *reinterpret_cast<float4*>(wi) = *(const float4*)&sm[WIH_OFF + ch4];
                float z[4][4];
                #pragma unroll
                for (int g = 0; g < 4; ++g) {
                    float xv = __ldg(&x[(b0 + g) * NSTEP + t]);
                    #pragma unroll
                    for (int q = 0; q < 4; ++q) z[g][q] = be[q] + xv * wi[q];
                }
                #pragma unroll
                for (int kq = 0; kq < 4; ++kq) {
                    float ev[4][4];
                    #pragma unroll
                    for (int g = 0; g < 4; ++g)
                        *reinterpret_cast<float4*>(ev[g]) =
                            *(const float4*)&sm[EHS_OFF + g * 16 + kq * 4];
                    #pragma unroll
                    for (int kk = 0; kk < 4; ++kk) {
                        int k = kq * 4 + kk;
                        float wv[4];
                        *reinterpret_cast<float4*>(wv) =
                            *(const float4*)&sm[WHH_OFF + ((k * 8 + c) * 16 + h) * 4];
                        #pragma unroll
                        for (int g = 0; g < 4; ++g) {
                            float e = ev[g][kk];
                            z[g][0] += e * wv[0];
                            z[g][1] += e * wv[1];
                            z[g][2] += e * wv[2];
                            z[g][3] += e * wv[3];
                        }
                    }
                }
                int lane2 = ((h & 7) >> 1);
                int q2 = (h & 1) | ((h >> 3) << 1);
                #pragma unroll
                for (int g = 0; g < 4; ++g) {
                    float ec = sm[ECS_OFF + g * 16 + h];
                    float c2 = sigf(z[g][1]) * ec + sigf(z[g][0]) * tanhfast(z[g][2]);
                    float hn = sigf(z[g][3]) * tanhfast(c2);
                    sm[RING_OFF + g * 128 + c * 16 + h] = hn;
                    sm[NC_OFF + g * 128 + c * 16 + h] = c2;
                    rh[((s * 9 + c) * 32 + ((g << 2) | lane2)) * 4 + q2] = __float2half(hn);
                }
            }
            if (tid < 4) {
                float xv = x[(b0 + tid) * NSTEP + t];
                float e = xv - sm[PRED_OFF + tid];
                sm[ERRH_OFF + tid * 10 + (t % 10)] = e;
                rh[((s * 9 + 8) * 32 + (tid << 2)) * 4] = __float2half(e);
            }
            asm volatile("membar.cta;" ::: "memory");
            asm volatile("bar.arrive 4, 512;" ::: "memory");
            asm volatile("bar.sync 1, 128;" ::: "memory");

            // ---- heads + theta ----
            if (tid < 32) {
                int g = tid >> 3, c = tid & 7;
                float sacc = sm[BOS_OFF + c];
                const float* rr = &sm[RING_OFF + g * 128 + c * 16];
                #pragma unroll
                for (int h = 0; h < 16; ++h) sacc += rr[h] * sm[WOS_OFF + c * 16 + h];
                sm[OSM_OFF + g * 8 + c] = sacc;
            } else if (tid < 36) {
                int g = tid - 32;
                float sacc = 0.0f;
                #pragma unroll
                for (int i2 = 0; i2 < 10; ++i2) sacc += fabsf(sm[ERRH_OFF + g * 10 + i2]);
                sm[THETA_OFF + g] = fminf(0.25f * sacc, 1.0f);
            }
            asm volatile("bar.sync 5, 512;" ::: "memory");

            if (tid < 64) {
                // ---- MLP2 ----
                int g = tid >> 4, j2 = tid & 15;
                {
                    const float4* e4 = reinterpret_cast<const float4*>(&sm[E1S_OFF + g * 64]);
                    const float4* w4 = reinterpret_cast<const float4*>(&sm[W2S_OFF + j2 * 68]);
                    float a[4] = {0.f, 0.f, 0.f, 0.f};
                    #pragma unroll
                    for (int kq = 0; kq < 16; ++kq) {
                        float4 e = e4[kq];
                        float4 w = w4[kq];
                        a[kq & 3] += e.x * w.x + e.y * w.y + e.z * w.z + e.w * w.w;
                    }
                    float sacc = sm[B2S_OFF + j2] + (a[0] + a[1]) + (a[2] + a[3]);
                    sm[AIS_OFF + g * 16 + j2] = fmaxf(sacc, 0.0f);
                }
                __syncwarp();
                // ---- agent: 2 fused LSTM layers ----
                int h = j2;
                #pragma unroll
                for (int l = 0; l < 2; ++l) {
                    const float* inp = (l == 0) ? &sm[AIS_OFF + g * 16]
                                                : &sm[AHS_OFF + g * 16];
                    const float* hp  = &sm[AHS_OFF + l * 64 + g * 16];
                    float iv[16], hv[16];
                    #pragma unroll
                    for (int kq = 0; kq < 4; ++kq) {
                        *reinterpret_cast<float4*>(&iv[kq * 4]) =
                            *(const float4*)&inp[kq * 4];
                        *reinterpret_cast<float4*>(&hv[kq * 4]) =
                            *(const float4*)&hp[kq * 4];
                    }
                    float z[4];
                    #pragma unroll
                    for (int q = 0; q < 4; ++q) {
                        const float4* wi4 = (const float4*)&sm[WAIH_OFF + l * 1024 + (q * 16 + h) * 16];
                        const float4* wh4 = (const float4*)&sm[WAHH_OFF + l * 1024 + (q * 16 + h) * 16];
                        float za = sm[BAC_OFF + l * 64 + q * 16 + h], zb = 0.0f;
                        #pragma unroll
                        for (int kq = 0; kq < 4; ++kq) {
                            float4 wi = wi4[kq], wh = wh4[kq];
                            za += iv[kq*4] * wi.x + iv[kq*4+1] * wi.y
                                + iv[kq*4+2] * wi.z + iv[kq*4+3] * wi.w;
                            zb += hv[kq*4] * wh.x + hv[kq*4+1] * wh.y
                                + hv[kq*4+2] * wh.z + hv[kq*4+3] * wh.w;
                        }
                        z[q] = za + zb;
                    }
                    float c2 = sigf(z[1]) * sm[ACS_OFF + l * 64 + g * 16 + h]
                             + sigf(z[0]) * tanhfast(z[2]);
                    float hn = sigf(z[3]) * tanhfast(c2);
                    sm[ACS_OFF + l * 64 + g * 16 + h] = c2;
                    sm[AHS_OFF + l * 64 + g * 16 + h] = hn;
                    __syncwarp();
                }
            }
            asm volatile("bar.sync 1, 128;" ::: "memory");

            // ---- gate + softmax + blend + pred + eh2/ec2 (one warp) ----
            if (tid < 32) {
                int g = tid >> 3, c = tid & 7;
                const float* a1p = &sm[AHS_OFF + 64 + g * 16];
                const float* wg  = &sm[WGS_OFF + c * 16];
                float za = sm[BGS_OFF + c], zb = 0.0f;
                #pragma unroll
                for (int k = 0; k < 8; ++k) {
                    za += a1p[2 * k] * wg[2 * k];
                    zb += a1p[2 * k + 1] * wg[2 * k + 1];
                }
                float zv = za + zb;
                float mx = zv;
                #pragma unroll
                for (int d = 1; d < 8; d <<= 1)
                    mx = fmaxf(mx, __shfl_xor_sync(0xffffffffu, mx, d));
                float ex = __expf(zv - mx);
                float ssum = ex;
                #pragma unroll
                for (int d = 1; d < 8; d <<= 1)
                    ssum += __shfl_xor_sync(0xffffffffu, ssum, d);
                float th = sm[THETA_OFF + g];
                float gf = ex * __fdividef(th, ssum)
                         + sm[GSM_OFF + g * 8 + c] * (1.0f - th);
                sm[GSM_OFF + g * 8 + c] = gf;
                float pv = gf * sm[OSM_OFF + g * 8 + c];
                #pragma unroll
                for (int d = 1; d < 8; d <<= 1)
                    pv += __shfl_xor_sync(0xffffffffu, pv, d);
                if (c == 0) {
                    sm[PRED_OFF + g] = pv;
                    out[(b0 + g) * NSTEP + t] = pv;
                }
                const float* rr = &sm[RING_OFF + g * 128];
                const float* nc = &sm[NC_OFF + g * 128];
                float se0 = 0.f, se1 = 0.f, sc0 = 0.f, sc1 = 0.f;
                #pragma unroll
                for (int cc = 0; cc < 8; ++cc) {
                    float gfb = __shfl_sync(0xffffffffu, gf, (g << 3) | cc);
                    se0 += gfb * rr[cc * 16 + 2 * c];
                    se1 += gfb * rr[cc * 16 + 2 * c + 1];
                    sc0 += gfb * nc[cc * 16 + 2 * c];
                    sc1 += gfb * nc[cc * 16 + 2 * c + 1];
                }
                sm[EHS_OFF + g * 16 + 2 * c]     = se0;
                sm[EHS_OFF + g * 16 + 2 * c + 1] = se1;
                sm[ECS_OFF + g * 16 + 2 * c]     = sc0;
                sm[ECS_OFF + g * 16 + 2 * c + 1] = sc1;
            }
            asm volatile("bar.sync 1, 128;" ::: "memory");

            head = s;
        }
    } else {
        // ====================== GEMM GROUP: warps 4-15 ======================
        const int w    = (tid >> 5) - 4;
        const int lane = tid & 31;
        const unsigned int* __restrict__ rhU =
            reinterpret_cast<const unsigned int*>(rh);
        const uint4* __restrict__ w01 =
            reinterpret_cast<const uint4*>(&sm[W01_OFF]);
        unsigned int stg;
        asm("{.reg .u64 t0; cvta.to.shared.u64 t0, %1; cvt.u32.u64 %0, t0;}"
            : "=r"(stg) : "l"(&sm[WSTG_OFF]));
        stg += (unsigned int)(w * 256 + lane) * 16;

        float d0[4] = {0,0,0,0}, d1[4] = {0,0,0,0};
        float d2[4] = {0,0,0,0}, d3[4] = {0,0,0,0};
        // t=0 prologue: ring slots all hold identical init state, value-safe
        prejobs_ca(0, w, lane, stg, rhU, d0, d1, d2, d3);

        int head = 0;
        for (int t = 0; t < NSTEP; ++t) {
            int s = head - 1; if (s < 0) s = 19;

            store_partials(&sm[PSB_OFF + w * 256], lane, d0, d1, d2, d3);

            asm volatile("bar.sync 4, 512;" ::: "memory");   // slot s ready

            float e0[4], e1[4], e2[4], e3[4];
            if (w >= 3) {
                // m=0 job (kb=w-3), slot s -> E1S(t), critical
                int kb0 = w - 3;
                #pragma unroll
                for (int i = 0; i < 4; ++i) { e0[i]=0.f; e1[i]=0.f; e2[i]=0.f; e3[i]=0.f; }
                int bofs = ((s * 9 + kb0) * 32 + lane) * 2;
                unsigned int bx = rhU[bofs], by = rhU[bofs + 1];
                const uint4* wq = w01 + kb0 * 128 + lane;
                uint4 a0 = wq[0], a1 = wq[32], a2 = wq[64], a3 = wq[96];
                MMA16816(e0, a0, bx, by);
                MMA16816(e1, a1, bx, by);
                MMA16816(e2, a2, bx, by);
                MMA16816(e3, a3, bx, by);
                store_partials(&sm[PSA_OFF + (w - 3) * 256], lane, e0, e1, e2, e3);
            }
            asm volatile("bar.sync 2, 384;" ::: "memory");
            // reduce: E1S = b1 + PSB(m>=2) + PSA(m=0) + PSA2(m=1 prev step)
            {
                int r = tid - 128;
                if (r < 256) {
                    int jr = r >> 2, gr = r & 3;
                    float sE = sm[B1S_OFF + jr];
                    #pragma unroll
                    for (int c = 0; c < 12; ++c)
                        sE += sm[PSB_OFF + (c * 64 + jr) * 4 + gr];
                    #pragma unroll
                    for (int c = 0; c < 9; ++c)
                        sE += sm[PSA_OFF + (c * 64 + jr) * 4 + gr];
                    #pragma unroll
                    for (int c = 0; c < 9; ++c)
                        sE += sm[PSA2_OFF + (c * 64 + jr) * 4 + gr];
                    sm[E1S_OFF + gr * 64 + jr] = fmaxf(sE, 0.0f);
                }
            }
            asm volatile("bar.sync 5, 512;" ::: "memory");   // publish E1S

            // m=1 job (kb=w), slot s -> PSA2 for step t+1
            if (w < 9) {
                #pragma unroll
                for (int i = 0; i < 4; ++i) { e0[i]=0.f; e1[i]=0.f; e2[i]=0.f; e3[i]=0.f; }
                int bofs = ((s * 9 + w) * 32 + lane) * 2;
                unsigned int bx = rhU[bofs], by = rhU[bofs + 1];
                const uint4* wq = w01 + (9 + w) * 128 + lane;
                uint4 a0 = wq[0], a1 = wq[32], a2 = wq[64], a3 = wq[96];
                MMA16816(e0, a0, bx, by);
                MMA16816(e1, a1, bx, by);
                MMA16816(e2, a2, bx, by);
                MMA16816(e3, a3, bx, by);
                store_partials(&sm[PSA2_OFF + w * 256], lane, e0, e1, e2, e3);
            }

            #pragma unroll
            for (int i = 0; i < 4; ++i) { d0[i] = 0.f; d1[i] = 0.f; d2[i] = 0.f; d3[i] = 0.f; }
            if (t < NSTEP - 1) {
                // prejobs for step t+1 with sP = s(t): row m reads slot
                // s(t)+m-1 = s(t+1)+m  (phase verified against R9/R10 dataflow)
                prejobs_ca(s, w, lane, stg, rhU, d0, d1, d2, d3);
            }
            head = s;
        }
    }
}

extern "C" void kernel_launch(void* const* d_in, const int* in_sizes, int n_in,
                              void* d_out, int out_size) {
    const float* x      = (const float*)d_in[0];
    const float* pred0  = (const float*)d_in[1];
    const float* gate0  = (const float*)d_in[2];
    const float* W_ih   = (const float*)d_in[3];
    const float* W_hh   = (const float*)d_in[4];
    const float* b_ih   = (const float*)d_in[5];
    const float* b_hh   = (const float*)d_in[6];
    const float* W_o    = (const float*)d_in[7];
    const float* b_o    = (const float*)d_in[8];
    const float* W1     = (const float*)d_in[9];
    const float* b1     = (const float*)d_in[10];
    const float* W2     = (const float*)d_in[11];
    const float* b2     = (const float*)d_in[12];
    const float* Wg     = (const float*)d_in[13];
    const float* bg     = (const float*)d_in[14];
    const float* Wa_ih  = (const float*)d_in[15];
    const float* Wa_hh  = (const float*)d_in[16];
    const float* ba_ih  = (const float*)d_in[17];
    const float* ba_hh  = (const float*)d_in[18];
    float* out = (float*)d_out;

    cudaFuncSetAttribute(mmoe_main, cudaFuncAttributeMaxDynamicSharedMemorySize, SMEM_BYTES);

    build_w1f<<<(W1F_U4 + 255) / 256, 256>>>(W1);
    mmoe_main<<<NCTA, NTHREADS, SMEM_BYTES>>>(
        x, pred0, gate0, W_ih, W_hh, b_ih, b_hh, W_o, b_o,
        W1, b1, W2, b2, Wg, bg, Wa_ih, Wa_hh, ba_ih, ba_hh, out);
}

// round 16
// speedup vs baseline: 1.1894x; 1.1894x over previous
#include <cuda_runtime.h>
#include <cuda_fp16.h>
#include <math.h>

#define NSTEP 256
#define G 4
#define NCTA 128
#define NTHREADS 512

#define W1F_JOBS 186
#define W1F_U4   (W1F_JOBS * 4 * 32)
__device__ uint4 g_W1f[W1F_U4];

// ---- shared memory layout (float offsets) ----
#define RING_OFF   0
#define RH_OFF     512
#define WHH_OFF    12032
#define WAIH_OFF   20224
#define WAHH_OFF   22272
#define W2S_OFF    24320
#define WIH_OFF    25408
#define BE_OFF     25920
#define PSB_OFF    26432
#define PSA_OFF    29504
#define PSA2_OFF   31808
#define E1S_OFF    34112
#define NC_OFF     34368
#define B1S_OFF    34880
#define BAC_OFF    34944
#define WGS_OFF    35072
#define WOS_OFF    35200
#define EHS_OFF    35328
#define ECS_OFF    35392
#define AHS_OFF    35456
#define ACS_OFF    35584
#define AIS_OFF    35712
#define GSM_OFF    35776
#define OSM_OFF    35808
#define ERRH_OFF   35840
#define B2S_OFF    35880
#define BGS_OFF    35896
#define BOS_OFF    35904
#define PRED_OFF   35912
#define THETA_OFF  35916
#define W01_OFF    35920
#define SMEM_FLOATS 45136
#define SMEM_BYTES  (SMEM_FLOATS * 4)   // 180,544 B

__device__ __forceinline__ float tanhfast(float v) {
    float r;
    asm("tanh.approx.f32 %0, %1;" : "=f"(r) : "f"(v));
    return r;
}
__device__ __forceinline__ float sigf(float v) {
    return fmaf(tanhfast(0.5f * v), 0.5f, 0.5f);
}

__global__ void build_w1f(const float* __restrict__ W1) {
    int idx = blockIdx.x * 256 + threadIdx.x;
    if (idx >= W1F_U4) return;
    int lane = idx & 31;
    int jt   = (idx >> 5) & 3;
    int job  = idx >> 7;
    int r  = lane >> 2;
    int tg = lane & 3;
    float f[8];
    #pragma unroll
    for (int i = 0; i < 8; ++i) f[i] = 0.0f;
    if (job < 180) {
        int m  = job / 9;
        int kb = job - m * 9;
        int j0 = jt * 16;
        int kbase = kb * 16;
        const int dj[8] = {r, r, r + 8, r + 8, r, r, r + 8, r + 8};
        const int dc[8] = {2*tg, 2*tg+1, 2*tg, 2*tg+1, 2*tg+8, 2*tg+9, 2*tg+8, 2*tg+9};
        #pragma unroll
        for (int i = 0; i < 8; ++i) {
            int kc = kbase + dc[i];
            if (kc < 129) f[i] = W1[(j0 + dj[i]) * 2580 + m * 129 + kc];
        }
    }
    __half h[8];
    #pragma unroll
    for (int i = 0; i < 8; ++i) h[i] = __float2half(f[i]);
    uint4 u;
    u.x = *reinterpret_cast<unsigned int*>(&h[0]);
    u.y = *reinterpret_cast<unsigned int*>(&h[2]);
    u.z = *reinterpret_cast<unsigned int*>(&h[4]);
    u.w = *reinterpret_cast<unsigned int*>(&h[6]);
    g_W1f[idx] = u;
}

#define MMA16816(d, a, bx, by) \
    asm volatile("mma.sync.aligned.m16n8k16.row.col.f32.f16.f16.f32 " \
        "{%0,%1,%2,%3}, {%4,%5,%6,%7}, {%8,%9}, {%0,%1,%2,%3};" \
        : "+f"(d[0]), "+f"(d[1]), "+f"(d[2]), "+f"(d[3]) \
        : "r"(a.x), "r"(a.y), "r"(a.z), "r"(a.w), "r"(bx), "r"(by))

// 14 pre-barrier jobs (m>=2) for step t+1, launched at end of step t with
// sP = s(t): row m reads slot sP+m-1 = s(t+1)+m  (lag-1 phase, validated R15).
// Plain-LDG weight loads: fully unrolled so ptxas front-batches the LDG.128s
// (validated at 1164us in the lag-2 kernel; faster than cp.async staging).
__device__ __forceinline__ void prejobs(int sP, int w, int lane,
    const unsigned int* __restrict__ rhU,
    float (&d0)[4], float (&d1)[4], float (&d2)[4], float (&d3)[4])
{
    const int J0 = 18 + w * 14;
    int m  = J0 / 9;
    int kb = J0 - m * 9;
    int slot = sP + m - 1;
    if (slot >= 20) slot -= 20;
    const uint4* __restrict__ wp = g_W1f + J0 * 128 + lane;
    #pragma unroll
    for (int it = 0; it < 14; ++it) {
        int bofs = ((slot * 9 + kb) * 32 + lane) * 2;
        unsigned int bx = rhU[bofs], by = rhU[bofs + 1];
        uint4 a0 = wp[it * 128];
        uint4 a1 = wp[it * 128 + 32];
        uint4 a2 = wp[it * 128 + 64];
        uint4 a3 = wp[it * 128 + 96];
        MMA16816(d0, a0, bx, by);
        MMA16816(d1, a1, bx, by);
        MMA16816(d2, a2, bx, by);
        MMA16816(d3, a3, bx, by);
        ++kb; if (kb == 9) { kb = 0; ++slot; if (slot == 20) slot = 0; }
    }
}

__device__ __forceinline__ void store_partials(float* __restrict__ base, int lane,
    const float (&d0)[4], const float (&d1)[4],
    const float (&d2)[4], const float (&d3)[4])
{
    int tg = lane & 3, gr = lane >> 2;
    if (tg < 2) {
        float* pb = base + 2 * tg;
        pb[(gr     ) * 4] = d0[0]; pb[(gr     ) * 4 + 1] = d0[1];
        pb[(gr +  8) * 4] = d0[2]; pb[(gr +  8) * 4 + 1] = d0[3];
        pb[(gr + 16) * 4] = d1[0]; pb[(gr + 16) * 4 + 1] = d1[1];
        pb[(gr + 24) * 4] = d1[2]; pb[(gr + 24) * 4 + 1] = d1[3];
        pb[(gr + 32) * 4] = d2[0]; pb[(gr + 32) * 4 + 1] = d2[1];
        pb[(gr + 40) * 4] = d2[2]; pb[(gr + 40) * 4 + 1] = d2[3];
        pb[(gr + 48) * 4] = d3[0]; pb[(gr + 48) * 4 + 1] = d3[1];
        pb[(gr + 56) * 4] = d3[2]; pb[(gr + 56) * 4 + 1] = d3[3];
    }
}

__global__ __launch_bounds__(NTHREADS, 1)
void mmoe_main(
    const float* __restrict__ x,      const float* __restrict__ pred0,
    const float* __restrict__ gate0,
    const float* __restrict__ W_ih,   const float* __restrict__ W_hh,
    const float* __restrict__ b_ih,   const float* __restrict__ b_hh,
    const float* __restrict__ W_o,    const float* __restrict__ b_o,
    const float* __restrict__ W1,     const float* __restrict__ b1,
    const float* __restrict__ W2,     const float* __restrict__ b2,
    const float* __restrict__ Wg,     const float* __restrict__ bg,
    const float* __restrict__ Wa_ih,  const float* __restrict__ Wa_hh,
    const float* __restrict__ ba_ih,  const float* __restrict__ ba_hh,
    float* __restrict__ out)
{
    extern __shared__ float sm[];
    __half* rh = reinterpret_cast<__half*>(&sm[RH_OFF]);
    const int tid = threadIdx.x;
    const int b0  = blockIdx.x * G;

    // ---------- init shared ----------
    if (tid < 512) sm[RING_OFF + tid] = 0.0f;
    for (int i = tid; i < 23040; i += NTHREADS) {
        int q = i & 3, ln = (i >> 2) & 31, kb = (i >> 7) % 9;
        bool is05 = (q == 0) && ((ln & 3) == 0) && (ln < 16) && (kb == 8);
        rh[i] = __float2half(is05 ? 0.5f : 0.0f);
    }
    for (int i = tid; i < 8192; i += NTHREADS) {
        int q = i & 3, h = (i >> 2) & 15, c = (i >> 6) & 7, k = i >> 9;
        sm[WHH_OFF + i] = W_hh[(c * 64 + q * 16 + h) * 16 + k];
    }
    {
        uint4* w01 = reinterpret_cast<uint4*>(&sm[W01_OFF]);
        for (int i = tid; i < 18 * 128; i += NTHREADS) w01[i] = g_W1f[i];
    }
    for (int i = tid; i < 2048; i += NTHREADS) {
        sm[WAIH_OFF + i] = Wa_ih[i];
        sm[WAHH_OFF + i] = Wa_hh[i];
    }
    for (int i = tid; i < 1088; i += NTHREADS) {
        int j2 = i / 68, k = i - j2 * 68;
        sm[W2S_OFF + i] = (k < 64) ? W2[j2 * 64 + k] : 0.0f;
    }
    if (tid < 512) {
        int q = tid & 3, h = (tid >> 2) & 15, c = tid >> 6;
        int gidx = c * 64 + q * 16 + h;
        sm[WIH_OFF + tid] = W_ih[gidx];
        sm[BE_OFF + tid]  = b_ih[gidx] + b_hh[gidx];
    }
    if (tid < 256) {
        int jj = tid >> 2;
        sm[PSA2_OFF + tid] = 0.5f * W1[jj * 2580 + 129 + 128];
        #pragma unroll
        for (int c = 1; c < 9; ++c) sm[PSA2_OFF + c * 256 + tid] = 0.0f;
    }
    if (tid < 128) {
        sm[BAC_OFF + tid] = ba_ih[tid] + ba_hh[tid];
        sm[WGS_OFF + tid] = Wg[tid];
        sm[WOS_OFF + tid] = W_o[tid];
        sm[AHS_OFF + tid] = 0.0f;
        sm[ACS_OFF + tid] = 0.0f;
    }
    if (tid < 64) { sm[B1S_OFF + tid] = b1[tid]; sm[EHS_OFF + tid] = 0.0f; sm[ECS_OFF + tid] = 0.0f; }
    if (tid < 40) sm[ERRH_OFF + tid] = 0.5f;
    if (tid < 32) sm[GSM_OFF + tid] = gate0[b0 * 8 + tid];
    if (tid < 16) sm[B2S_OFF + tid] = b2[tid];
    if (tid < 8)  { sm[BGS_OFF + tid] = bg[tid]; sm[BOS_OFF + tid] = b_o[tid]; }
    if (tid < 4)  sm[PRED_OFF + tid] = pred0[b0 + tid];
    __syncthreads();

    if (tid < 128) {
        // ====================== SMALL GROUP: warps 0-3 ======================
        int head = 0;
        for (int t = 0; t < NSTEP; ++t) {
            int s = head - 1; if (s < 0) s = 19;

            // ---- phase 2: experts ----
            {
                int c = tid >> 4, h = tid & 15;
                int ch4 = (c * 16 + h) * 4;
                float be[4], wi[4];
                *reinterpret_cast<float4*>(be) = *(const float4*)&sm[BE_OFF + ch4];
                *reinterpret_cast<float4*>(wi) = *(const float4*)&sm[WIH_OFF + ch4];
                float z[4][4];
                #pragma unroll
                for (int g = 0; g < 4; ++g) {
                    float xv = __ldg(&x[(b0 + g) * NSTEP + t]);
                    #pragma unroll
                    for (int q = 0; q < 4; ++q) z[g][q] = be[q] + xv * wi[q];
                }
                #pragma unroll
                for (int kq = 0; kq < 4; ++kq) {
                    float ev[4][4];
                    #pragma unroll
                    for (int g = 0; g < 4; ++g)
                        *reinterpret_cast<float4*>(ev[g]) =
                            *(const float4*)&sm[EHS_OFF + g * 16 + kq * 4];
                    #pragma unroll
                    for (int kk = 0; kk < 4; ++kk) {
                        int k = kq * 4 + kk;
                        float wv[4];
                        *reinterpret_cast<float4*>(wv) =
                            *(const float4*)&sm[WHH_OFF + ((k * 8 + c) * 16 + h) * 4];
                        #pragma unroll
                        for (int g = 0; g < 4; ++g) {
                            float e = ev[g][kk];
                            z[g][0] += e * wv[0];
                            z[g][1] += e * wv[1];
                            z[g][2] += e * wv[2];
                            z[g][3] += e * wv[3];
                        }
                    }
                }
                int lane2 = ((h & 7) >> 1);
                int q2 = (h & 1) | ((h >> 3) << 1);
                #pragma unroll
                for (int g = 0; g < 4; ++g) {
                    float ec = sm[ECS_OFF + g * 16 + h];
                    float c2 = sigf(z[g][1]) * ec + sigf(z[g][0]) * tanhfast(z[g][2]);
                    float hn = sigf(z[g][3]) * tanhfast(c2);
                    sm[RING_OFF + g * 128 + c * 16 + h] = hn;
                    sm[NC_OFF + g * 128 + c * 16 + h] = c2;
                    rh[((s * 9 + c) * 32 + ((g << 2) | lane2)) * 4 + q2] = __float2half(hn);
                }
            }
            if (tid < 4) {
                float xv = x[(b0 + tid) * NSTEP + t];
                float e = xv - sm[PRED_OFF + tid];
                sm[ERRH_OFF + tid * 10 + (t % 10)] = e;
                rh[((s * 9 + 8) * 32 + (tid << 2)) * 4] = __float2half(e);
            }
            // release ring writes, then signal (bar.arrive has no fence)
            asm volatile("membar.cta;" ::: "memory");
            asm volatile("bar.arrive 4, 512;" ::: "memory");
            asm volatile("bar.sync 1, 128;" ::: "memory");

            // ---- heads + theta (hidden under GEMM m=0 job + reduce) ----
            if (tid < 32) {
                int g = tid >> 3, c = tid & 7;
                float sacc = sm[BOS_OFF + c];
                const float* rr = &sm[RING_OFF + g * 128 + c * 16];
                #pragma unroll
                for (int h = 0; h < 16; ++h) sacc += rr[h] * sm[WOS_OFF + c * 16 + h];
                sm[OSM_OFF + g * 8 + c] = sacc;
            } else if (tid < 36) {
                int g = tid - 32;
                float sacc = 0.0f;
                #pragma unroll
                for (int i2 = 0; i2 < 10; ++i2) sacc += fabsf(sm[ERRH_OFF + g * 10 + i2]);
                sm[THETA_OFF + g] = fminf(0.25f * sacc, 1.0f);
            }
            asm volatile("bar.sync 5, 512;" ::: "memory");   // E1S published

            if (tid < 64) {
                // ---- MLP2 ----
                int g = tid >> 4, j2 = tid & 15;
                {
                    const float4* e4 = reinterpret_cast<const float4*>(&sm[E1S_OFF + g * 64]);
                    const float4* w4 = reinterpret_cast<const float4*>(&sm[W2S_OFF + j2 * 68]);
                    float a[4] = {0.f, 0.f, 0.f, 0.f};
                    #pragma unroll
                    for (int kq = 0; kq < 16; ++kq) {
                        float4 e = e4[kq];
                        float4 w = w4[kq];
                        a[kq & 3] += e.x * w.x + e.y * w.y + e.z * w.z + e.w * w.w;
                    }
                    float sacc = sm[B2S_OFF + j2] + (a[0] + a[1]) + (a[2] + a[3]);
                    sm[AIS_OFF + g * 16 + j2] = fmaxf(sacc, 0.0f);
                }
                __syncwarp();
                // ---- agent: 2 fused LSTM layers ----
                int h = j2;
                #pragma unroll
                for (int l = 0; l < 2; ++l) {
                    const float* inp = (l == 0) ? &sm[AIS_OFF + g * 16]
                                                : &sm[AHS_OFF + g * 16];
                    const float* hp  = &sm[AHS_OFF + l * 64 + g * 16];
                    float iv[16], hv[16];
                    #pragma unroll
                    for (int kq = 0; kq < 4; ++kq) {
                        *reinterpret_cast<float4*>(&iv[kq * 4]) =
                            *(const float4*)&inp[kq * 4];
                        *reinterpret_cast<float4*>(&hv[kq * 4]) =
                            *(const float4*)&hp[kq * 4];
                    }
                    float z[4];
                    #pragma unroll
                    for (int q = 0; q < 4; ++q) {
                        const float4* wi4 = (const float4*)&sm[WAIH_OFF + l * 1024 + (q * 16 + h) * 16];
                        const float4* wh4 = (const float4*)&sm[WAHH_OFF + l * 1024 + (q * 16 + h) * 16];
                        float za = sm[BAC_OFF + l * 64 + q * 16 + h], zb = 0.0f;
                        #pragma unroll
                        for (int kq = 0; kq < 4; ++kq) {
                            float4 wi = wi4[kq], wh = wh4[kq];
                            za += iv[kq*4] * wi.x + iv[kq*4+1] * wi.y
                                + iv[kq*4+2] * wi.z + iv[kq*4+3] * wi.w;
                            zb += hv[kq*4] * wh.x + hv[kq*4+1] * wh.y
                                + hv[kq*4+2] * wh.z + hv[kq*4+3] * wh.w;
                        }
                        z[q] = za + zb;
                    }
                    float c2 = sigf(z[1]) * sm[ACS_OFF + l * 64 + g * 16 + h]
                             + sigf(z[0]) * tanhfast(z[2]);
                    float hn = sigf(z[3]) * tanhfast(c2);
                    sm[ACS_OFF + l * 64 + g * 16 + h] = c2;
                    sm[AHS_OFF + l * 64 + g * 16 + h] = hn;
                    __syncwarp();
                }
            }
            asm volatile("bar.sync 1, 128;" ::: "memory");

            // ---- gate + softmax + blend + pred + eh2/ec2 (one warp) ----
            if (tid < 32) {
                int g = tid >> 3, c = tid & 7;
                const float* a1p = &sm[AHS_OFF + 64 + g * 16];
                const float* wg  = &sm[WGS_OFF + c * 16];
                float za = sm[BGS_OFF + c], zb = 0.0f;
                #pragma unroll
                for (int k = 0; k < 8; ++k) {
                    za += a1p[2 * k] * wg[2 * k];
                    zb += a1p[2 * k + 1] * wg[2 * k + 1];
                }
                float zv = za + zb;
                float mx = zv;
                #pragma unroll
                for (int d = 1; d < 8; d <<= 1)
                    mx = fmaxf(mx, __shfl_xor_sync(0xffffffffu, mx, d));
                float ex = __expf(zv - mx);
                float ssum = ex;
                #pragma unroll
                for (int d = 1; d < 8; d <<= 1)
                    ssum += __shfl_xor_sync(0xffffffffu, ssum, d);
                float th = sm[THETA_OFF + g];
                float gf = ex * __fdividef(th, ssum)
                         + sm[GSM_OFF + g * 8 + c] * (1.0f - th);
                sm[GSM_OFF + g * 8 + c] = gf;
                float pv = gf * sm[OSM_OFF + g * 8 + c];
                #pragma unroll
                for (int d = 1; d < 8; d <<= 1)
                    pv += __shfl_xor_sync(0xffffffffu, pv, d);
                if (c == 0) {
                    sm[PRED_OFF + g] = pv;
                    out[(b0 + g) * NSTEP + t] = pv;
                }
                const float* rr = &sm[RING_OFF + g * 128];
                const float* nc = &sm[NC_OFF + g * 128];
                float se0 = 0.f, se1 = 0.f, sc0 = 0.f, sc1 = 0.f;
                #pragma unroll
                for (int cc = 0; cc < 8; ++cc) {
                    float gfb = __shfl_sync(0xffffffffu, gf, (g << 3) | cc);
                    se0 += gfb * rr[cc * 16 + 2 * c];
                    se1 += gfb * rr[cc * 16 + 2 * c + 1];
                    sc0 += gfb * nc[cc * 16 + 2 * c];
                    sc1 += gfb * nc[cc * 16 + 2 * c + 1];
                }
                sm[EHS_OFF + g * 16 + 2 * c]     = se0;
                sm[EHS_OFF + g * 16 + 2 * c + 1] = se1;
                sm[ECS_OFF + g * 16 + 2 * c]     = sc0;
                sm[ECS_OFF + g * 16 + 2 * c + 1] = sc1;
            }
            asm volatile("bar.sync 1, 128;" ::: "memory");

            head = s;
        }
    } else {
        // ====================== GEMM GROUP: warps 4-15 ======================
        const int w    = (tid >> 5) - 4;
        const int lane = tid & 31;
        const unsigned int* __restrict__ rhU =
            reinterpret_cast<const unsigned int*>(rh);
        const uint4* __restrict__ w01 =
            reinterpret_cast<const uint4*>(&sm[W01_OFF]);

        float d0[4] = {0,0,0,0}, d1[4] = {0,0,0,0};
        float d2[4] = {0,0,0,0}, d3[4] = {0,0,0,0};
        // t=0 prologue: ring slots all hold identical init state, value-safe
        prejobs(0, w, lane, rhU, d0, d1, d2, d3);

        int head = 0;
        for (int t = 0; t < NSTEP; ++t) {
            int s = head - 1; if (s < 0) s = 19;

            store_partials(&sm[PSB_OFF + w * 256], lane, d0, d1, d2, d3);

            asm volatile("bar.sync 4, 512;" ::: "memory");   // slot s ready

            float e0[4], e1[4], e2[4], e3[4];
            if (w >= 3) {
                // m=0 job (kb=w-3), slot s -> E1S(t), critical
                int kb0 = w - 3;
                #pragma unroll
                for (int i = 0; i < 4; ++i) { e0[i]=0.f; e1[i]=0.f; e2[i]=0.f; e3[i]=0.f; }
                int bofs = ((s * 9 + kb0) * 32 + lane) * 2;
                unsigned int bx = rhU[bofs], by = rhU[bofs + 1];
                const uint4* wq = w01 + kb0 * 128 + lane;
                uint4 a0 = wq[0], a1 = wq[32], a2 = wq[64], a3 = wq[96];
                MMA16816(e0, a0, bx, by);
                MMA16816(e1, a1, bx, by);
                MMA16816(e2, a2, bx, by);
                MMA16816(e3, a3, bx, by);
                store_partials(&sm[PSA_OFF + (w - 3) * 256], lane, e0, e1, e2, e3);
            }
            asm volatile("bar.sync 2, 384;" ::: "memory");
            // reduce: E1S = b1 + PSB(m>=2) + PSA(m=0) + PSA2(m=1 prev step)
            {
                int r = tid - 128;
                if (r < 256) {
                    int jr = r >> 2, gr = r & 3;
                    float sE = sm[B1S_OFF + jr];
                    #pragma unroll
                    for (int c = 0; c < 12; ++c)
                        sE += sm[PSB_OFF + (c * 64 + jr) * 4 + gr];
                    #pragma unroll
                    for (int c = 0; c < 9; ++c)
                        sE += sm[PSA_OFF + (c * 64 + jr) * 4 + gr];
                    #pragma unroll
                    for (int c = 0; c < 9; ++c)
                        sE += sm[PSA2_OFF + (c * 64 + jr) * 4 + gr];
                    sm[E1S_OFF + gr * 64 + jr] = fmaxf(sE, 0.0f);
                }
            }
            asm volatile("bar.sync 5, 512;" ::: "memory");   // publish E1S

            // m=1 job (kb=w), slot s -> PSA2 for step t+1 (off critical window)
            if (w < 9) {
                #pragma unroll
                for (int i = 0; i < 4; ++i) { e0[i]=0.f; e1[i]=0.f; e2[i]=0.f; e3[i]=0.f; }
                int bofs = ((s * 9 + w) * 32 + lane) * 2;
                unsigned int bx = rhU[bofs], by = rhU[bofs + 1];
                const uint4* wq = w01 + (9 + w) * 128 + lane;
                uint4 a0 = wq[0], a1 = wq[32], a2 = wq[64], a3 = wq[96];
                MMA16816(e0, a0, bx, by);
                MMA16816(e1, a1, bx, by);
                MMA16816(e2, a2, bx, by);
                MMA16816(e3, a3, bx, by);
                store_partials(&sm[PSA2_OFF + w * 256], lane, e0, e1, e2, e3);
            }

            #pragma unroll
            for (int i = 0; i < 4; ++i) { d0[i] = 0.f; d1[i] = 0.f; d2[i] = 0.f; d3[i] = 0.f; }
            if (t < NSTEP - 1) {
                // prejobs for step t+1 with sP = s(t) (lag-1 phase, validated R15)
                prejobs(s, w, lane, rhU, d0, d1, d2, d3);
            }
            head = s;
        }
    }
}

extern "C" void kernel_launch(void* const* d_in, const int* in_sizes, int n_in,
                              void* d_out, int out_size) {
    const float* x      = (const float*)d_in[0];
    const float* pred0  = (const float*)d_in[1];
    const float* gate0  = (const float*)d_in[2];
    const float* W_ih   = (const float*)d_in[3];
    const float* W_hh   = (const float*)d_in[4];
    const float* b_ih   = (const float*)d_in[5];
    const float* b_hh   = (const float*)d_in[6];
    const float* W_o    = (const float*)d_in[7];
    const float* b_o    = (const float*)d_in[8];
    const float* W1     = (const float*)d_in[9];
    const float* b1     = (const float*)d_in[10];
    const float* W2     = (const float*)d_in[11];
    const float* b2     = (const float*)d_in[12];
    const float* Wg     = (const float*)d_in[13];
    const float* bg     = (const float*)d_in[14];
    const float* Wa_ih  = (const float*)d_in[15];
    const float* Wa_hh  = (const float*)d_in[16];
    const float* ba_ih  = (const float*)d_in[17];
    const float* ba_hh  = (const float*)d_in[18];
    float* out = (float*)d_out;

    cudaFuncSetAttribute(mmoe_main, cudaFuncAttributeMaxDynamicSharedMemorySize, SMEM_BYTES);

    build_w1f<<<(W1F_U4 + 255) / 256, 256>>>(W1);
    mmoe_main<<<NCTA, NTHREADS, SMEM_BYTES>>>(
        x, pred0, gate0, W_ih, W_hh, b_ih, b_hh, W_o, b_o,
        W1, b1, W2, b2, Wg, bg, Wa_ih, Wa_hh, ba_ih, ba_hh, out);
}